// round 13
// baseline (speedup 1.0000x reference)
#include <cuda_runtime.h>
#include <cuda_fp16.h>
#include <cstdint>

#define N_NODES 100000
#define N_EDGES 1600000
#define N_EP    200000
#define N_EN    200000
#define IN_CH   256
#define HID     128
#define N_CLS   10
#define CAP     64
#define NODE_OUT_ELEMS (N_NODES * N_CLS)

// ---------------- static device scratch (no allocation allowed) ----------------
__device__ int    g_cursor[N_NODES];                  // degree counts / bucket cursor
__device__ int    g_srcbuf[(size_t)N_NODES * CAP];    // 25.6 MB
__device__ __half g_tmph[(size_t)N_NODES * 128];      // 25.6 MB (x@W buffer, fp16)
__device__ __half g_hh[(size_t)N_NODES * 128];        // 25.6 MB (h buffer, fp16)

// ---------------- graph preprocessing ----------------
__global__ void k_zero() {
    int i = blockIdx.x * blockDim.x + threadIdx.x;
    if (i < N_NODES) g_cursor[i] = 0;
}

__global__ void k_bucket(const int* __restrict__ ei) {
    int i = blockIdx.x * blockDim.x + threadIdx.x;
    if (i < N_EDGES) {
        int d = ei[N_EDGES + i];
        int slot = atomicAdd(&g_cursor[d], 1);
        if (slot < CAP) g_srcbuf[(size_t)d * CAP + slot] = ei[i];
    }
}

// ---------------- fp16 tensor-core GEMM: g_tmph[N,128] = fp16(A[N,K] @ W[K,128]) ----------------
__device__ __forceinline__ uint32_t packh2(float a, float b) {
    __half2 h = __floats2half2_rn(a, b);
    return *(uint32_t*)&h;
}

// 128x128 tile, 256 threads = 8 warps (4m x 2n), warp tile 32x64, m16n8k16 fp16.
template <int K, bool USE_H>
__global__ void __launch_bounds__(256, 2) k_gemm_f16(const float* __restrict__ A,
                                                     const float* __restrict__ W) {
    constexpr int KC = 32;
    constexpr int KC2 = 16;
    __shared__ uint32_t Asp[KC2][136];
    __shared__ uint32_t Bsp[KC2][136];
    int node0 = blockIdx.x * 128;
    int tid  = threadIdx.x;
    int wid  = tid >> 5, lane = tid & 31;
    int wm   = wid >> 1, wn = wid & 1;
    int rb   = wm * 32,  cb = wn * 64;
    int gid  = lane >> 2, tig = lane & 3;

    float acc[2][8][4];
#pragma unroll
    for (int mi = 0; mi < 2; mi++)
#pragma unroll
        for (int ni = 0; ni < 8; ni++)
#pragma unroll
            for (int c = 0; c < 4; c++) acc[mi][ni][c] = 0.0f;

    for (int kc = 0; kc < K; kc += KC) {
#pragma unroll
        for (int j = 0; j < 2; j++) {
            int e = tid + j * 256;
            int row = e >> 2, quad = e & 3;
            int gr = node0 + row; if (gr >= N_NODES) gr = N_NODES - 1;
            if (USE_H) {
                uint4 u = *(const uint4*)&g_hh[(size_t)gr * K + kc + quad * 8];
                Asp[quad * 4 + 0][row] = u.x;
                Asp[quad * 4 + 1][row] = u.y;
                Asp[quad * 4 + 2][row] = u.z;
                Asp[quad * 4 + 3][row] = u.w;
            } else {
                const float* src = &A[(size_t)gr * K + kc + quad * 8];
                float4 v0 = *(const float4*)src;
                float4 v1 = *(const float4*)(src + 4);
                Asp[quad * 4 + 0][row] = packh2(v0.x, v0.y);
                Asp[quad * 4 + 1][row] = packh2(v0.z, v0.w);
                Asp[quad * 4 + 2][row] = packh2(v1.x, v1.y);
                Asp[quad * 4 + 3][row] = packh2(v1.z, v1.w);
            }
        }
#pragma unroll
        for (int j = 0; j < 2; j++) {
            int e = tid + j * 256;
            int kr2 = e >> 5, c4 = (e & 31) * 4;
            float4 lo = *(const float4*)&W[(size_t)(kc + 2 * kr2) * 128 + c4];
            float4 hi = *(const float4*)&W[(size_t)(kc + 2 * kr2 + 1) * 128 + c4];
            uint4 o;
            o.x = packh2(lo.x, hi.x);
            o.y = packh2(lo.y, hi.y);
            o.z = packh2(lo.z, hi.z);
            o.w = packh2(lo.w, hi.w);
            *(uint4*)&Bsp[kr2][c4] = o;
        }
        __syncthreads();

#pragma unroll
        for (int k0 = 0; k0 < KC2; k0 += 8) {
            uint32_t a[2][4];
#pragma unroll
            for (int mi = 0; mi < 2; mi++) {
                int r0 = rb + mi * 16 + gid;
                a[mi][0] = Asp[k0 + tig    ][r0];
                a[mi][1] = Asp[k0 + tig    ][r0 + 8];
                a[mi][2] = Asp[k0 + tig + 4][r0];
                a[mi][3] = Asp[k0 + tig + 4][r0 + 8];
            }
#pragma unroll
            for (int ni = 0; ni < 8; ni++) {
                uint32_t b0 = Bsp[k0 + tig    ][cb + ni * 8 + gid];
                uint32_t b1 = Bsp[k0 + tig + 4][cb + ni * 8 + gid];
#pragma unroll
                for (int mi = 0; mi < 2; mi++) {
                    asm volatile(
                        "mma.sync.aligned.m16n8k16.row.col.f32.f16.f16.f32 "
                        "{%0,%1,%2,%3}, {%4,%5,%6,%7}, {%8,%9}, {%0,%1,%2,%3};"
                        : "+f"(acc[mi][ni][0]), "+f"(acc[mi][ni][1]),
                          "+f"(acc[mi][ni][2]), "+f"(acc[mi][ni][3])
                        : "r"(a[mi][0]), "r"(a[mi][1]), "r"(a[mi][2]), "r"(a[mi][3]),
                          "r"(b0), "r"(b1));
                }
            }
        }
        __syncthreads();
    }

#pragma unroll
    for (int mi = 0; mi < 2; mi++) {
        int r0 = node0 + rb + mi * 16 + gid;
#pragma unroll
        for (int ni = 0; ni < 8; ni++) {
            int c0 = cb + ni * 8 + tig * 2;
            if (r0 < N_NODES)
                *(uint32_t*)&g_tmph[(size_t)r0 * 128 + c0] = packh2(acc[mi][ni][0], acc[mi][ni][1]);
            if (r0 + 8 < N_NODES)
                *(uint32_t*)&g_tmph[(size_t)(r0 + 8) * 128 + c0] = packh2(acc[mi][ni][2], acc[mi][ni][3]);
        }
    }
}

// ---------------- aggregation with block-staged (src, weight) pairs ----------------
// dinv computed on the fly: rsqrtf(deg+1), no separate kernel or buffer.
__device__ __forceinline__ void fma8(uint4 u, float wt, float acc[8]) {
    __half2 h0 = *(__half2*)&u.x, h1 = *(__half2*)&u.y;
    __half2 h2 = *(__half2*)&u.z, h3 = *(__half2*)&u.w;
    float2 f0 = __half22float2(h0), f1 = __half22float2(h1);
    float2 f2 = __half22float2(h2), f3 = __half22float2(h3);
    acc[0] += f0.x * wt; acc[1] += f0.y * wt; acc[2] += f1.x * wt; acc[3] += f1.y * wt;
    acc[4] += f2.x * wt; acc[5] += f2.y * wt; acc[6] += f3.x * wt; acc[7] += f3.y * wt;
}

struct SW { int s; float w; };

template <typename EPILOG>
__device__ __forceinline__ void agg_block(const float* __restrict__ bias, EPILOG epi) {
    __shared__ SW    pairs[16][CAP];     // 8 KB
    __shared__ int   scnt[16];
    __shared__ float sdv[16];

    int tid = threadIdx.x;
    int nb = blockIdx.x * 16;

    if (tid < 16) {
        int c = g_cursor[nb + tid];
        scnt[tid] = c > CAP ? CAP : c;
        sdv[tid] = rsqrtf((float)c + 1.0f);
    }
    __syncthreads();

#pragma unroll
    for (int j = 0; j < 4; j++) {
        int i = tid + j * 256;
        int n = i >> 6, e = i & 63;
        int s = nb + n;
        float w = 0.0f;
        if (e < scnt[n]) {
            s = __ldg(&g_srcbuf[(size_t)(nb + n) * CAP + e]);
            float ds = (float)__ldg(&g_cursor[s]);
            w = rsqrtf(ds + 1.0f) * sdv[n];
        }
        pairs[n][e].s = s;
        pairs[n][e].w = w;
    }
    __syncthreads();

    int lane = tid & 31;
    int nloc = 2 * (tid >> 5) + (lane >> 4);
    int sl = lane & 15;
    int nd = nb + nloc;

    const uint4* xwh = (const uint4*)g_tmph;
    float dv = sdv[nloc];
    float acc[8];
#pragma unroll
    for (int j = 0; j < 8; j++) acc[j] = 0.0f;

    fma8(__ldg(&xwh[(size_t)nd * 16 + sl]), dv * dv, acc);

    int cnt = scnt[nloc];
    int cnt_other = __shfl_xor_sync(0xffffffffu, cnt, 16);
    int cntmax = cnt > cnt_other ? cnt : cnt_other;
    cntmax = (cntmax + 3) & ~3;

    for (int e = 0; e < cntmax; e += 4) {
        SW p0 = pairs[nloc][e];
        SW p1 = pairs[nloc][e + 1];
        SW p2 = pairs[nloc][e + 2];
        SW p3 = pairs[nloc][e + 3];
        uint4 v0 = __ldg(&xwh[(size_t)p0.s * 16 + sl]);
        uint4 v1 = __ldg(&xwh[(size_t)p1.s * 16 + sl]);
        uint4 v2 = __ldg(&xwh[(size_t)p2.s * 16 + sl]);
        uint4 v3 = __ldg(&xwh[(size_t)p3.s * 16 + sl]);
        fma8(v0, p0.w, acc);
        fma8(v1, p1.w, acc);
        fma8(v2, p2.w, acc);
        fma8(v3, p3.w, acc);
    }

    float4 b0 = *(const float4*)&bias[sl * 8];
    float4 b1 = *(const float4*)&bias[sl * 8 + 4];
    acc[0] += b0.x; acc[1] += b0.y; acc[2] += b0.z; acc[3] += b0.w;
    acc[4] += b1.x; acc[5] += b1.y; acc[6] += b1.z; acc[7] += b1.w;

    epi(nd, sl, acc);
}

__device__ __forceinline__ void store_h16(int nd, int sl, const float hv[8]) {
    uint4 packed;
    packed.x = packh2(hv[0], hv[1]);
    packed.y = packh2(hv[2], hv[3]);
    packed.z = packh2(hv[4], hv[5]);
    packed.w = packh2(hv[6], hv[7]);
    *(uint4*)&g_hh[(size_t)nd * 128 + sl * 8] = packed;
}

// layer-1: h1 = relu(agg + b1), stored fp16 (gemm2 input)
__global__ void __launch_bounds__(256) k_agg_relu(const float* __restrict__ bias) {
    agg_block(bias, [](int nd, int sl, float acc[8]) {
#pragma unroll
        for (int j = 0; j < 8; j++) acc[j] = fmaxf(acc[j], 0.0f);
        store_h16(nd, sl, acc);
    });
}

// layer-2 aggregation + node head; h2 stored fp16 (link head input)
__global__ void __launch_bounds__(256) k_agg_nodehead(const float* __restrict__ bias,
                               const float* __restrict__ Wc, const float* __restrict__ bc,
                               float* __restrict__ out) {
    agg_block(bias, [Wc, bc, out](int nd, int sl, float hv[8]) {
        store_h16(nd, sl, hv);

        float r[8];
#pragma unroll
        for (int j = 0; j < 8; j++) r[j] = fmaxf(hv[j], 0.0f);
        int k0 = sl * 8;

        float logits[N_CLS];
#pragma unroll
        for (int c = 0; c < N_CLS; c++) {
            float p = 0.0f;
#pragma unroll
            for (int j = 0; j < 8; j++) p += r[j] * __ldg(&Wc[(k0 + j) * N_CLS + c]);
#pragma unroll
            for (int o = 8; o > 0; o >>= 1) p += __shfl_xor_sync(0xffffffffu, p, o);
            logits[c] = p + __ldg(&bc[c]);
        }

        float m = logits[0];
#pragma unroll
        for (int c = 1; c < N_CLS; c++) m = fmaxf(m, logits[c]);
        float se = 0.0f;
#pragma unroll
        for (int c = 0; c < N_CLS; c++) se += expf(logits[c] - m);
        float lse = m + logf(se);

        if (sl < N_CLS) {
            float val = logits[0];
#pragma unroll
            for (int c = 1; c < N_CLS; c++) if (sl == c) val = logits[c];
            out[(size_t)nd * N_CLS + sl] = val - lse;
        }
    });
}

// ---------------- link head: 2 edges per warp, fp16 h gathers ----------------
__global__ void k_link(const int* __restrict__ ep, const int* __restrict__ en,
                       const float* __restrict__ Wl, const float* __restrict__ bl,
                       float* __restrict__ out) {
    int gw = (blockIdx.x * blockDim.x + threadIdx.x) >> 5;
    int lane = threadIdx.x & 31;
    int eidx = 2 * gw + (lane >> 4);
    int sl = lane & 15;
    if (eidx >= N_EP + N_EN) return;

    int s, d;
    float* o;
    if (eidx < N_EP) {
        s = ep[eidx]; d = ep[N_EP + eidx]; o = out + eidx;
    } else {
        int e2 = eidx - N_EP;
        s = en[e2]; d = en[N_EN + e2]; o = out + N_EP + e2;
    }

    const uint4* xh = (const uint4*)g_hh;
    uint4 us = __ldg(&xh[(size_t)s * 16 + sl]);
    uint4 ud = __ldg(&xh[(size_t)d * 16 + sl]);

    float hs[8] = {0,0,0,0,0,0,0,0}, hd[8] = {0,0,0,0,0,0,0,0};
    fma8(us, 1.0f, hs);
    fma8(ud, 1.0f, hd);

    float4 w0 = *(const float4*)&Wl[sl * 8];
    float4 w1 = *(const float4*)&Wl[sl * 8 + 4];
    float4 w2 = *(const float4*)&Wl[128 + sl * 8];
    float4 w3 = *(const float4*)&Wl[128 + sl * 8 + 4];

    float p = hs[0] * w0.x + hs[1] * w0.y + hs[2] * w0.z + hs[3] * w0.w
            + hs[4] * w1.x + hs[5] * w1.y + hs[6] * w1.z + hs[7] * w1.w
            + hd[0] * w2.x + hd[1] * w2.y + hd[2] * w2.z + hd[3] * w2.w
            + hd[4] * w3.x + hd[5] * w3.y + hd[6] * w3.z + hd[7] * w3.w;
#pragma unroll
    for (int o2 = 8; o2 > 0; o2 >>= 1) p += __shfl_xor_sync(0xffffffffu, p, o2);

    if (sl == 0) *o = p + bl[0];
}

// ---------------- launch ----------------
extern "C" void kernel_launch(void* const* d_in, const int* in_sizes, int n_in,
                              void* d_out, int out_size) {
    const float* x   = (const float*)d_in[0];
    const int*   ei  = (const int*)d_in[1];
    const int*   ep  = (const int*)d_in[2];
    const int*   en  = (const int*)d_in[3];
    const float* W1  = (const float*)d_in[4];
    const float* b1  = (const float*)d_in[5];
    const float* W2  = (const float*)d_in[6];
    const float* b2  = (const float*)d_in[7];
    const float* Wc  = (const float*)d_in[8];
    const float* bc  = (const float*)d_in[9];
    const float* Wl  = (const float*)d_in[10];
    const float* bl  = (const float*)d_in[11];
    float* out = (float*)d_out;

    const int GEMM_GRID = (N_NODES + 127) / 128;
    const int AGG_GRID  = N_NODES / 16;
    const int LINK_GRID = ((N_EP + N_EN) / 2 + 7) / 8;

    // graph preprocessing (cursor doubles as degree count; dinv computed in agg)
    k_zero<<<(N_NODES + 255) / 256, 256>>>();
    k_bucket<<<N_EDGES / 256, 256>>>(ei);

    // layer 1: tmph = fp16(x @ W1) ; h1 = relu(agg(tmph) + b1) -> fp16
    k_gemm_f16<IN_CH, false><<<GEMM_GRID, 256>>>(x, W1);
    k_agg_relu<<<AGG_GRID, 256>>>(b1);   // 4th launch -> profiled next round

    // layer 2: tmph = fp16(h1 @ W2) ; agg + node head fused, h2 -> fp16
    k_gemm_f16<HID, true><<<GEMM_GRID, 256>>>(nullptr, W2);
    k_agg_nodehead<<<AGG_GRID, 256>>>(b2, Wc, bc, out);

    // link head
    k_link<<<LINK_GRID, 256>>>(ep, en, Wl, bl, out + NODE_OUT_ELEMS);
}

// round 14
// speedup vs baseline: 1.0547x; 1.0547x over previous
#include <cuda_runtime.h>
#include <cuda_fp16.h>
#include <cstdint>

#define N_NODES 100000
#define N_EDGES 1600000
#define N_EP    200000
#define N_EN    200000
#define IN_CH   256
#define HID     128
#define N_CLS   10
#define CAP     64
#define NODE_OUT_ELEMS (N_NODES * N_CLS)

// ---------------- static device scratch (no allocation allowed) ----------------
__device__ int    g_cursor[N_NODES];                  // degree counts / bucket cursor
__device__ float  g_dinv[N_NODES];
__device__ int    g_srcbuf[(size_t)N_NODES * CAP];    // 25.6 MB
__device__ __half g_tmph[(size_t)N_NODES * 128];      // 25.6 MB (x@W buffer, fp16)
__device__ __half g_hh[(size_t)N_NODES * 128];        // 25.6 MB (h buffer, fp16)

// ---------------- graph preprocessing ----------------
__global__ void k_zero() {
    int i = blockIdx.x * blockDim.x + threadIdx.x;
    if (i < N_NODES) g_cursor[i] = 0;
}

__global__ void k_bucket(const int* __restrict__ ei) {
    int i = blockIdx.x * blockDim.x + threadIdx.x;
    if (i < N_EDGES) {
        int d = ei[N_EDGES + i];
        int slot = atomicAdd(&g_cursor[d], 1);
        if (slot < CAP) g_srcbuf[(size_t)d * CAP + slot] = ei[i];
    }
}

__global__ void k_dinv() {
    int i = blockIdx.x * blockDim.x + threadIdx.x;
    if (i < N_NODES) g_dinv[i] = rsqrtf((float)g_cursor[i] + 1.0f);
}

// ---------------- fp16 tensor-core GEMM: g_tmph[N,128] = fp16(A[N,K] @ W[K,128]) ----------------
__device__ __forceinline__ uint32_t packh2(float a, float b) {
    __half2 h = __floats2half2_rn(a, b);
    return *(uint32_t*)&h;
}

// 128x128 tile, 256 threads = 8 warps (4m x 2n), warp tile 32x64, m16n8k16 fp16.
template <int K, bool USE_H>
__global__ void __launch_bounds__(256, 2) k_gemm_f16(const float* __restrict__ A,
                                                     const float* __restrict__ W) {
    constexpr int KC = 32;
    constexpr int KC2 = 16;
    __shared__ uint32_t Asp[KC2][136];
    __shared__ uint32_t Bsp[KC2][136];
    int node0 = blockIdx.x * 128;
    int tid  = threadIdx.x;
    int wid  = tid >> 5, lane = tid & 31;
    int wm   = wid >> 1, wn = wid & 1;
    int rb   = wm * 32,  cb = wn * 64;
    int gid  = lane >> 2, tig = lane & 3;

    float acc[2][8][4];
#pragma unroll
    for (int mi = 0; mi < 2; mi++)
#pragma unroll
        for (int ni = 0; ni < 8; ni++)
#pragma unroll
            for (int c = 0; c < 4; c++) acc[mi][ni][c] = 0.0f;

    for (int kc = 0; kc < K; kc += KC) {
#pragma unroll
        for (int j = 0; j < 2; j++) {
            int e = tid + j * 256;
            int row = e >> 2, quad = e & 3;
            int gr = node0 + row; if (gr >= N_NODES) gr = N_NODES - 1;
            if (USE_H) {
                uint4 u = *(const uint4*)&g_hh[(size_t)gr * K + kc + quad * 8];
                Asp[quad * 4 + 0][row] = u.x;
                Asp[quad * 4 + 1][row] = u.y;
                Asp[quad * 4 + 2][row] = u.z;
                Asp[quad * 4 + 3][row] = u.w;
            } else {
                const float* src = &A[(size_t)gr * K + kc + quad * 8];
                float4 v0 = *(const float4*)src;
                float4 v1 = *(const float4*)(src + 4);
                Asp[quad * 4 + 0][row] = packh2(v0.x, v0.y);
                Asp[quad * 4 + 1][row] = packh2(v0.z, v0.w);
                Asp[quad * 4 + 2][row] = packh2(v1.x, v1.y);
                Asp[quad * 4 + 3][row] = packh2(v1.z, v1.w);
            }
        }
#pragma unroll
        for (int j = 0; j < 2; j++) {
            int e = tid + j * 256;
            int kr2 = e >> 5, c4 = (e & 31) * 4;
            float4 lo = *(const float4*)&W[(size_t)(kc + 2 * kr2) * 128 + c4];
            float4 hi = *(const float4*)&W[(size_t)(kc + 2 * kr2 + 1) * 128 + c4];
            uint4 o;
            o.x = packh2(lo.x, hi.x);
            o.y = packh2(lo.y, hi.y);
            o.z = packh2(lo.z, hi.z);
            o.w = packh2(lo.w, hi.w);
            *(uint4*)&Bsp[kr2][c4] = o;
        }
        __syncthreads();

#pragma unroll
        for (int k0 = 0; k0 < KC2; k0 += 8) {
            uint32_t a[2][4];
#pragma unroll
            for (int mi = 0; mi < 2; mi++) {
                int r0 = rb + mi * 16 + gid;
                a[mi][0] = Asp[k0 + tig    ][r0];
                a[mi][1] = Asp[k0 + tig    ][r0 + 8];
                a[mi][2] = Asp[k0 + tig + 4][r0];
                a[mi][3] = Asp[k0 + tig + 4][r0 + 8];
            }
#pragma unroll
            for (int ni = 0; ni < 8; ni++) {
                uint32_t b0 = Bsp[k0 + tig    ][cb + ni * 8 + gid];
                uint32_t b1 = Bsp[k0 + tig + 4][cb + ni * 8 + gid];
#pragma unroll
                for (int mi = 0; mi < 2; mi++) {
                    asm volatile(
                        "mma.sync.aligned.m16n8k16.row.col.f32.f16.f16.f32 "
                        "{%0,%1,%2,%3}, {%4,%5,%6,%7}, {%8,%9}, {%0,%1,%2,%3};"
                        : "+f"(acc[mi][ni][0]), "+f"(acc[mi][ni][1]),
                          "+f"(acc[mi][ni][2]), "+f"(acc[mi][ni][3])
                        : "r"(a[mi][0]), "r"(a[mi][1]), "r"(a[mi][2]), "r"(a[mi][3]),
                          "r"(b0), "r"(b1));
                }
            }
        }
        __syncthreads();
    }

#pragma unroll
    for (int mi = 0; mi < 2; mi++) {
        int r0 = node0 + rb + mi * 16 + gid;
#pragma unroll
        for (int ni = 0; ni < 8; ni++) {
            int c0 = cb + ni * 8 + tig * 2;
            if (r0 < N_NODES)
                *(uint32_t*)&g_tmph[(size_t)r0 * 128 + c0] = packh2(acc[mi][ni][0], acc[mi][ni][1]);
            if (r0 + 8 < N_NODES)
                *(uint32_t*)&g_tmph[(size_t)(r0 + 8) * 128 + c0] = packh2(acc[mi][ni][2], acc[mi][ni][3]);
        }
    }
}

// ---------------- aggregation with block-staged (src, weight) pairs ----------------
__device__ __forceinline__ void fma8(uint4 u, float wt, float acc[8]) {
    __half2 h0 = *(__half2*)&u.x, h1 = *(__half2*)&u.y;
    __half2 h2 = *(__half2*)&u.z, h3 = *(__half2*)&u.w;
    float2 f0 = __half22float2(h0), f1 = __half22float2(h1);
    float2 f2 = __half22float2(h2), f3 = __half22float2(h3);
    acc[0] += f0.x * wt; acc[1] += f0.y * wt; acc[2] += f1.x * wt; acc[3] += f1.y * wt;
    acc[4] += f2.x * wt; acc[5] += f2.y * wt; acc[6] += f3.x * wt; acc[7] += f3.y * wt;
}

struct SW { int s; float w; };

template <typename EPILOG>
__device__ __forceinline__ void agg_block(const float* __restrict__ bias, EPILOG epi) {
    __shared__ SW    pairs[16][CAP];     // 8 KB
    __shared__ int   scnt[16];
    __shared__ float sdv[16];

    int tid = threadIdx.x;
    int nb = blockIdx.x * 16;

    if (tid < 16) {
        int c = g_cursor[nb + tid];
        scnt[tid] = c > CAP ? CAP : c;
        sdv[tid] = g_dinv[nb + tid];
    }
    __syncthreads();

#pragma unroll
    for (int j = 0; j < 4; j++) {
        int i = tid + j * 256;
        int n = i >> 6, e = i & 63;
        int s = nb + n;
        float w = 0.0f;
        if (e < scnt[n]) {
            s = __ldg(&g_srcbuf[(size_t)(nb + n) * CAP + e]);
            w = __ldg(&g_dinv[s]) * sdv[n];
        }
        pairs[n][e].s = s;
        pairs[n][e].w = w;
    }
    __syncthreads();

    int lane = tid & 31;
    int nloc = 2 * (tid >> 5) + (lane >> 4);
    int sl = lane & 15;
    int nd = nb + nloc;

    const uint4* xwh = (const uint4*)g_tmph;
    float dv = sdv[nloc];
    float acc[8];
#pragma unroll
    for (int j = 0; j < 8; j++) acc[j] = 0.0f;

    fma8(__ldg(&xwh[(size_t)nd * 16 + sl]), dv * dv, acc);

    int cnt = scnt[nloc];
    int cnt_other = __shfl_xor_sync(0xffffffffu, cnt, 16);
    int cntmax = cnt > cnt_other ? cnt : cnt_other;
    cntmax = (cntmax + 3) & ~3;

    for (int e = 0; e < cntmax; e += 4) {
        SW p0 = pairs[nloc][e];
        SW p1 = pairs[nloc][e + 1];
        SW p2 = pairs[nloc][e + 2];
        SW p3 = pairs[nloc][e + 3];
        uint4 v0 = __ldg(&xwh[(size_t)p0.s * 16 + sl]);
        uint4 v1 = __ldg(&xwh[(size_t)p1.s * 16 + sl]);
        uint4 v2 = __ldg(&xwh[(size_t)p2.s * 16 + sl]);
        uint4 v3 = __ldg(&xwh[(size_t)p3.s * 16 + sl]);
        fma8(v0, p0.w, acc);
        fma8(v1, p1.w, acc);
        fma8(v2, p2.w, acc);
        fma8(v3, p3.w, acc);
    }

    float4 b0 = *(const float4*)&bias[sl * 8];
    float4 b1 = *(const float4*)&bias[sl * 8 + 4];
    acc[0] += b0.x; acc[1] += b0.y; acc[2] += b0.z; acc[3] += b0.w;
    acc[4] += b1.x; acc[5] += b1.y; acc[6] += b1.z; acc[7] += b1.w;

    epi(nd, sl, acc);
}

__device__ __forceinline__ void store_h16(int nd, int sl, const float hv[8]) {
    uint4 packed;
    packed.x = packh2(hv[0], hv[1]);
    packed.y = packh2(hv[2], hv[3]);
    packed.z = packh2(hv[4], hv[5]);
    packed.w = packh2(hv[6], hv[7]);
    *(uint4*)&g_hh[(size_t)nd * 128 + sl * 8] = packed;
}

// layer-1: h1 = relu(agg + b1), stored fp16 (gemm2 input)
__global__ void __launch_bounds__(256) k_agg_relu(const float* __restrict__ bias) {
    agg_block(bias, [](int nd, int sl, float acc[8]) {
#pragma unroll
        for (int j = 0; j < 8; j++) acc[j] = fmaxf(acc[j], 0.0f);
        store_h16(nd, sl, acc);
    });
}

// layer-2 aggregation + node head; h2 stored fp16 (link head input)
__global__ void __launch_bounds__(256) k_agg_nodehead(const float* __restrict__ bias,
                               const float* __restrict__ Wc, const float* __restrict__ bc,
                               float* __restrict__ out) {
    agg_block(bias, [Wc, bc, out](int nd, int sl, float hv[8]) {
        store_h16(nd, sl, hv);

        float r[8];
#pragma unroll
        for (int j = 0; j < 8; j++) r[j] = fmaxf(hv[j], 0.0f);
        int k0 = sl * 8;

        // per-lane partial logits, vectorized float2 Wc loads (rows are 8B-aligned)
        float l[N_CLS];
#pragma unroll
        for (int c = 0; c < N_CLS; c++) l[c] = 0.0f;
#pragma unroll
        for (int j = 0; j < 8; j++) {
            const float2* wrow = (const float2*)&Wc[(k0 + j) * N_CLS];
            float rj = r[j];
#pragma unroll
            for (int v = 0; v < 5; v++) {
                float2 wv = __ldg(&wrow[v]);
                l[2 * v]     += rj * wv.x;
                l[2 * v + 1] += rj * wv.y;
            }
        }
        // butterfly reduce over the 16-lane half-warp
#pragma unroll
        for (int c = 0; c < N_CLS; c++) {
#pragma unroll
            for (int o = 8; o > 0; o >>= 1)
                l[c] += __shfl_xor_sync(0xffffffffu, l[c], o);
        }
        // add bias (vectorized)
        {
            const float2* bv = (const float2*)bc;
#pragma unroll
            for (int v = 0; v < 5; v++) {
                float2 b2 = __ldg(&bv[v]);
                l[2 * v] += b2.x;
                l[2 * v + 1] += b2.y;
            }
        }

        float m = l[0];
#pragma unroll
        for (int c = 1; c < N_CLS; c++) m = fmaxf(m, l[c]);
        float se = 0.0f;
#pragma unroll
        for (int c = 0; c < N_CLS; c++) se += expf(l[c] - m);
        float lse = m + logf(se);

        if (sl < N_CLS) {
            float val = l[0];
#pragma unroll
            for (int c = 1; c < N_CLS; c++) if (sl == c) val = l[c];
            out[(size_t)nd * N_CLS + sl] = val - lse;
        }
    });
}

// ---------------- link head: 2 edges per warp, fp16 h gathers ----------------
__global__ void k_link(const int* __restrict__ ep, const int* __restrict__ en,
                       const float* __restrict__ Wl, const float* __restrict__ bl,
                       float* __restrict__ out) {
    int gw = (blockIdx.x * blockDim.x + threadIdx.x) >> 5;
    int lane = threadIdx.x & 31;
    int eidx = 2 * gw + (lane >> 4);
    int sl = lane & 15;
    if (eidx >= N_EP + N_EN) return;

    int s, d;
    float* o;
    if (eidx < N_EP) {
        s = ep[eidx]; d = ep[N_EP + eidx]; o = out + eidx;
    } else {
        int e2 = eidx - N_EP;
        s = en[e2]; d = en[N_EN + e2]; o = out + N_EP + e2;
    }

    const uint4* xh = (const uint4*)g_hh;
    uint4 us = __ldg(&xh[(size_t)s * 16 + sl]);
    uint4 ud = __ldg(&xh[(size_t)d * 16 + sl]);

    float hs[8] = {0,0,0,0,0,0,0,0}, hd[8] = {0,0,0,0,0,0,0,0};
    fma8(us, 1.0f, hs);
    fma8(ud, 1.0f, hd);

    float4 w0 = *(const float4*)&Wl[sl * 8];
    float4 w1 = *(const float4*)&Wl[sl * 8 + 4];
    float4 w2 = *(const float4*)&Wl[128 + sl * 8];
    float4 w3 = *(const float4*)&Wl[128 + sl * 8 + 4];

    float p = hs[0] * w0.x + hs[1] * w0.y + hs[2] * w0.z + hs[3] * w0.w
            + hs[4] * w1.x + hs[5] * w1.y + hs[6] * w1.z + hs[7] * w1.w
            + hd[0] * w2.x + hd[1] * w2.y + hd[2] * w2.z + hd[3] * w2.w
            + hd[4] * w3.x + hd[5] * w3.y + hd[6] * w3.z + hd[7] * w3.w;
#pragma unroll
    for (int o2 = 8; o2 > 0; o2 >>= 1) p += __shfl_xor_sync(0xffffffffu, p, o2);

    if (sl == 0) *o = p + bl[0];
}

// ---------------- launch ----------------
extern "C" void kernel_launch(void* const* d_in, const int* in_sizes, int n_in,
                              void* d_out, int out_size) {
    const float* x   = (const float*)d_in[0];
    const int*   ei  = (const int*)d_in[1];
    const int*   ep  = (const int*)d_in[2];
    const int*   en  = (const int*)d_in[3];
    const float* W1  = (const float*)d_in[4];
    const float* b1  = (const float*)d_in[5];
    const float* W2  = (const float*)d_in[6];
    const float* b2  = (const float*)d_in[7];
    const float* Wc  = (const float*)d_in[8];
    const float* bc  = (const float*)d_in[9];
    const float* Wl  = (const float*)d_in[10];
    const float* bl  = (const float*)d_in[11];
    float* out = (float*)d_out;

    const int GEMM_GRID = (N_NODES + 127) / 128;
    const int AGG_GRID  = N_NODES / 16;
    const int LINK_GRID = ((N_EP + N_EN) / 2 + 7) / 8;

    // graph preprocessing (cursor doubles as degree count)
    k_zero<<<(N_NODES + 255) / 256, 256>>>();
    k_bucket<<<N_EDGES / 256, 256>>>(ei);
    k_dinv<<<(N_NODES + 255) / 256, 256>>>();

    // layer 1: tmph = fp16(x @ W1) ; h1 = relu(agg(tmph) + b1) -> fp16
    k_gemm_f16<IN_CH, false><<<GEMM_GRID, 256>>>(x, W1);
    k_agg_relu<<<AGG_GRID, 256>>>(b1);

    // layer 2: tmph = fp16(h1 @ W2) ; agg + node head fused, h2 -> fp16
    k_gemm_f16<HID, true><<<GEMM_GRID, 256>>>(nullptr, W2);
    k_agg_nodehead<<<AGG_GRID, 256>>>(b2, Wc, bc, out);

    // link head
    k_link<<<LINK_GRID, 256>>>(ep, en, Wl, bl, out + NODE_OUT_ELEMS);
}

// round 15
// speedup vs baseline: 1.1481x; 1.0886x over previous
#include <cuda_runtime.h>
#include <cuda_fp16.h>
#include <cstdint>

#define N_NODES 100000
#define N_EDGES 1600000
#define N_EP    200000
#define N_EN    200000
#define IN_CH   256
#define HID     128
#define N_CLS   10
#define CAP     64
#define NODE_OUT_ELEMS (N_NODES * N_CLS)

// ---------------- static device scratch (no allocation allowed) ----------------
__device__ int    g_cursor[N_NODES];                  // degree counts / bucket cursor
__device__ float  g_dinv[N_NODES];
__device__ int    g_srcbuf[(size_t)N_NODES * CAP];    // 25.6 MB
__device__ __half g_tmph[(size_t)N_NODES * 128];      // 25.6 MB (x@W buffer, fp16)
__device__ __half g_hh[(size_t)N_NODES * 128];        // 25.6 MB (h1 buffer, fp16)
__device__ float  g_lta[N_NODES];                     // dot(h2, Wl[:128])
__device__ float  g_ltb[N_NODES];                     // dot(h2, Wl[128:])

// ---------------- graph preprocessing ----------------
__global__ void k_zero() {
    int i = blockIdx.x * blockDim.x + threadIdx.x;
    if (i < N_NODES) g_cursor[i] = 0;
}

// 4 edges per thread: int4 loads for dst/src streams, 4 atomics in flight
__global__ void k_bucket(const int* __restrict__ ei) {
    int base = (blockIdx.x * blockDim.x + threadIdx.x) * 4;
    if (base >= N_EDGES) return;
    int4 ds = *(const int4*)&ei[N_EDGES + base];
    int4 ss = *(const int4*)&ei[base];
    int d[4] = {ds.x, ds.y, ds.z, ds.w};
    int s[4] = {ss.x, ss.y, ss.z, ss.w};
#pragma unroll
    for (int j = 0; j < 4; j++) {
        int slot = atomicAdd(&g_cursor[d[j]], 1);
        if (slot < CAP) g_srcbuf[(size_t)d[j] * CAP + slot] = s[j];
    }
}

__global__ void k_dinv() {
    int i = blockIdx.x * blockDim.x + threadIdx.x;
    if (i < N_NODES) g_dinv[i] = rsqrtf((float)g_cursor[i] + 1.0f);
}

// ---------------- fp16 tensor-core GEMM: g_tmph[N,128] = fp16(A[N,K] @ W[K,128]) ----------------
__device__ __forceinline__ uint32_t packh2(float a, float b) {
    __half2 h = __floats2half2_rn(a, b);
    return *(uint32_t*)&h;
}

// 128x128 tile, 256 threads = 8 warps (4m x 2n), warp tile 32x64, m16n8k16 fp16.
template <int K, bool USE_H>
__global__ void __launch_bounds__(256, 2) k_gemm_f16(const float* __restrict__ A,
                                                     const float* __restrict__ W) {
    constexpr int KC = 32;
    constexpr int KC2 = 16;
    __shared__ uint32_t Asp[KC2][136];
    __shared__ uint32_t Bsp[KC2][136];
    int node0 = blockIdx.x * 128;
    int tid  = threadIdx.x;
    int wid  = tid >> 5, lane = tid & 31;
    int wm   = wid >> 1, wn = wid & 1;
    int rb   = wm * 32,  cb = wn * 64;
    int gid  = lane >> 2, tig = lane & 3;

    float acc[2][8][4];
#pragma unroll
    for (int mi = 0; mi < 2; mi++)
#pragma unroll
        for (int ni = 0; ni < 8; ni++)
#pragma unroll
            for (int c = 0; c < 4; c++) acc[mi][ni][c] = 0.0f;

    for (int kc = 0; kc < K; kc += KC) {
#pragma unroll
        for (int j = 0; j < 2; j++) {
            int e = tid + j * 256;
            int row = e >> 2, quad = e & 3;
            int gr = node0 + row; if (gr >= N_NODES) gr = N_NODES - 1;
            if (USE_H) {
                uint4 u = *(const uint4*)&g_hh[(size_t)gr * K + kc + quad * 8];
                Asp[quad * 4 + 0][row] = u.x;
                Asp[quad * 4 + 1][row] = u.y;
                Asp[quad * 4 + 2][row] = u.z;
                Asp[quad * 4 + 3][row] = u.w;
            } else {
                const float* src = &A[(size_t)gr * K + kc + quad * 8];
                float4 v0 = *(const float4*)src;
                float4 v1 = *(const float4*)(src + 4);
                Asp[quad * 4 + 0][row] = packh2(v0.x, v0.y);
                Asp[quad * 4 + 1][row] = packh2(v0.z, v0.w);
                Asp[quad * 4 + 2][row] = packh2(v1.x, v1.y);
                Asp[quad * 4 + 3][row] = packh2(v1.z, v1.w);
            }
        }
#pragma unroll
        for (int j = 0; j < 2; j++) {
            int e = tid + j * 256;
            int kr2 = e >> 5, c4 = (e & 31) * 4;
            float4 lo = *(const float4*)&W[(size_t)(kc + 2 * kr2) * 128 + c4];
            float4 hi = *(const float4*)&W[(size_t)(kc + 2 * kr2 + 1) * 128 + c4];
            uint4 o;
            o.x = packh2(lo.x, hi.x);
            o.y = packh2(lo.y, hi.y);
            o.z = packh2(lo.z, hi.z);
            o.w = packh2(lo.w, hi.w);
            *(uint4*)&Bsp[kr2][c4] = o;
        }
        __syncthreads();

#pragma unroll
        for (int k0 = 0; k0 < KC2; k0 += 8) {
            uint32_t a[2][4];
#pragma unroll
            for (int mi = 0; mi < 2; mi++) {
                int r0 = rb + mi * 16 + gid;
                a[mi][0] = Asp[k0 + tig    ][r0];
                a[mi][1] = Asp[k0 + tig    ][r0 + 8];
                a[mi][2] = Asp[k0 + tig + 4][r0];
                a[mi][3] = Asp[k0 + tig + 4][r0 + 8];
            }
#pragma unroll
            for (int ni = 0; ni < 8; ni++) {
                uint32_t b0 = Bsp[k0 + tig    ][cb + ni * 8 + gid];
                uint32_t b1 = Bsp[k0 + tig + 4][cb + ni * 8 + gid];
#pragma unroll
                for (int mi = 0; mi < 2; mi++) {
                    asm volatile(
                        "mma.sync.aligned.m16n8k16.row.col.f32.f16.f16.f32 "
                        "{%0,%1,%2,%3}, {%4,%5,%6,%7}, {%8,%9}, {%0,%1,%2,%3};"
                        : "+f"(acc[mi][ni][0]), "+f"(acc[mi][ni][1]),
                          "+f"(acc[mi][ni][2]), "+f"(acc[mi][ni][3])
                        : "r"(a[mi][0]), "r"(a[mi][1]), "r"(a[mi][2]), "r"(a[mi][3]),
                          "r"(b0), "r"(b1));
                }
            }
        }
        __syncthreads();
    }

#pragma unroll
    for (int mi = 0; mi < 2; mi++) {
        int r0 = node0 + rb + mi * 16 + gid;
#pragma unroll
        for (int ni = 0; ni < 8; ni++) {
            int c0 = cb + ni * 8 + tig * 2;
            if (r0 < N_NODES)
                *(uint32_t*)&g_tmph[(size_t)r0 * 128 + c0] = packh2(acc[mi][ni][0], acc[mi][ni][1]);
            if (r0 + 8 < N_NODES)
                *(uint32_t*)&g_tmph[(size_t)(r0 + 8) * 128 + c0] = packh2(acc[mi][ni][2], acc[mi][ni][3]);
        }
    }
}

// ---------------- aggregation with block-staged (src, weight) pairs ----------------
__device__ __forceinline__ void fma8(uint4 u, float wt, float acc[8]) {
    __half2 h0 = *(__half2*)&u.x, h1 = *(__half2*)&u.y;
    __half2 h2 = *(__half2*)&u.z, h3 = *(__half2*)&u.w;
    float2 f0 = __half22float2(h0), f1 = __half22float2(h1);
    float2 f2 = __half22float2(h2), f3 = __half22float2(h3);
    acc[0] += f0.x * wt; acc[1] += f0.y * wt; acc[2] += f1.x * wt; acc[3] += f1.y * wt;
    acc[4] += f2.x * wt; acc[5] += f2.y * wt; acc[6] += f3.x * wt; acc[7] += f3.y * wt;
}

struct SW { int s; float w; };

template <typename EPILOG>
__device__ __forceinline__ void agg_block(const float* __restrict__ bias, EPILOG epi) {
    __shared__ SW    pairs[16][CAP];     // 8 KB
    __shared__ int   scnt[16];
    __shared__ float sdv[16];

    int tid = threadIdx.x;
    int nb = blockIdx.x * 16;

    if (tid < 16) {
        int c = g_cursor[nb + tid];
        scnt[tid] = c > CAP ? CAP : c;
        sdv[tid] = g_dinv[nb + tid];
    }
    __syncthreads();

#pragma unroll
    for (int j = 0; j < 4; j++) {
        int i = tid + j * 256;
        int n = i >> 6, e = i & 63;
        int s = nb + n;
        float w = 0.0f;
        if (e < scnt[n]) {
            s = __ldg(&g_srcbuf[(size_t)(nb + n) * CAP + e]);
            w = __ldg(&g_dinv[s]) * sdv[n];
        }
        pairs[n][e].s = s;
        pairs[n][e].w = w;
    }
    __syncthreads();

    int lane = tid & 31;
    int nloc = 2 * (tid >> 5) + (lane >> 4);
    int sl = lane & 15;
    int nd = nb + nloc;

    const uint4* xwh = (const uint4*)g_tmph;
    float dv = sdv[nloc];
    float acc[8];
#pragma unroll
    for (int j = 0; j < 8; j++) acc[j] = 0.0f;

    fma8(__ldg(&xwh[(size_t)nd * 16 + sl]), dv * dv, acc);

    int cnt = scnt[nloc];
    int cnt_other = __shfl_xor_sync(0xffffffffu, cnt, 16);
    int cntmax = cnt > cnt_other ? cnt : cnt_other;
    cntmax = (cntmax + 3) & ~3;

    for (int e = 0; e < cntmax; e += 4) {
        SW p0 = pairs[nloc][e];
        SW p1 = pairs[nloc][e + 1];
        SW p2 = pairs[nloc][e + 2];
        SW p3 = pairs[nloc][e + 3];
        uint4 v0 = __ldg(&xwh[(size_t)p0.s * 16 + sl]);
        uint4 v1 = __ldg(&xwh[(size_t)p1.s * 16 + sl]);
        uint4 v2 = __ldg(&xwh[(size_t)p2.s * 16 + sl]);
        uint4 v3 = __ldg(&xwh[(size_t)p3.s * 16 + sl]);
        fma8(v0, p0.w, acc);
        fma8(v1, p1.w, acc);
        fma8(v2, p2.w, acc);
        fma8(v3, p3.w, acc);
    }

    float4 b0 = *(const float4*)&bias[sl * 8];
    float4 b1 = *(const float4*)&bias[sl * 8 + 4];
    acc[0] += b0.x; acc[1] += b0.y; acc[2] += b0.z; acc[3] += b0.w;
    acc[4] += b1.x; acc[5] += b1.y; acc[6] += b1.z; acc[7] += b1.w;

    epi(nd, sl, acc);
}

// layer-1: h1 = relu(agg + b1), stored fp16 (gemm2 input)
__global__ void __launch_bounds__(256) k_agg_relu(const float* __restrict__ bias) {
    agg_block(bias, [](int nd, int sl, float acc[8]) {
#pragma unroll
        for (int j = 0; j < 8; j++) acc[j] = fmaxf(acc[j], 0.0f);
        uint4 packed;
        packed.x = packh2(acc[0], acc[1]);
        packed.y = packh2(acc[2], acc[3]);
        packed.z = packh2(acc[4], acc[5]);
        packed.w = packh2(acc[6], acc[7]);
        *(uint4*)&g_hh[(size_t)nd * 128 + sl * 8] = packed;
    });
}

// layer-2 aggregation + node head + link-dot precompute (no h2 store needed)
__global__ void __launch_bounds__(256) k_agg_nodehead(const float* __restrict__ bias,
                               const float* __restrict__ Wc, const float* __restrict__ bc,
                               const float* __restrict__ Wl,
                               float* __restrict__ out) {
    agg_block(bias, [Wc, bc, Wl, out](int nd, int sl, float hv[8]) {
        // ---- link-dot precompute: a = h2 . Wl[:128], b = h2 . Wl[128:] ----
        {
            float4 w0 = *(const float4*)&Wl[sl * 8];
            float4 w1 = *(const float4*)&Wl[sl * 8 + 4];
            float4 w2 = *(const float4*)&Wl[128 + sl * 8];
            float4 w3 = *(const float4*)&Wl[128 + sl * 8 + 4];
            float la = hv[0] * w0.x + hv[1] * w0.y + hv[2] * w0.z + hv[3] * w0.w
                     + hv[4] * w1.x + hv[5] * w1.y + hv[6] * w1.z + hv[7] * w1.w;
            float lb = hv[0] * w2.x + hv[1] * w2.y + hv[2] * w2.z + hv[3] * w2.w
                     + hv[4] * w3.x + hv[5] * w3.y + hv[6] * w3.z + hv[7] * w3.w;
#pragma unroll
            for (int o = 8; o > 0; o >>= 1) {
                la += __shfl_xor_sync(0xffffffffu, la, o);
                lb += __shfl_xor_sync(0xffffffffu, lb, o);
            }
            if (sl == 0) { g_lta[nd] = la; g_ltb[nd] = lb; }
        }

        // ---- node head ----
        float r[8];
#pragma unroll
        for (int j = 0; j < 8; j++) r[j] = fmaxf(hv[j], 0.0f);
        int k0 = sl * 8;

        float l[N_CLS];
#pragma unroll
        for (int c = 0; c < N_CLS; c++) l[c] = 0.0f;
#pragma unroll
        for (int j = 0; j < 8; j++) {
            const float2* wrow = (const float2*)&Wc[(k0 + j) * N_CLS];
            float rj = r[j];
#pragma unroll
            for (int v = 0; v < 5; v++) {
                float2 wv = __ldg(&wrow[v]);
                l[2 * v]     += rj * wv.x;
                l[2 * v + 1] += rj * wv.y;
            }
        }
#pragma unroll
        for (int c = 0; c < N_CLS; c++) {
#pragma unroll
            for (int o = 8; o > 0; o >>= 1)
                l[c] += __shfl_xor_sync(0xffffffffu, l[c], o);
        }
        {
            const float2* bv = (const float2*)bc;
#pragma unroll
            for (int v = 0; v < 5; v++) {
                float2 b2 = __ldg(&bv[v]);
                l[2 * v] += b2.x;
                l[2 * v + 1] += b2.y;
            }
        }

        float m = l[0];
#pragma unroll
        for (int c = 1; c < N_CLS; c++) m = fmaxf(m, l[c]);
        float se = 0.0f;
#pragma unroll
        for (int c = 0; c < N_CLS; c++) se += expf(l[c] - m);
        float lse = m + logf(se);

        if (sl < N_CLS) {
            float val = l[0];
#pragma unroll
            for (int c = 1; c < N_CLS; c++) if (sl == c) val = l[c];
            out[(size_t)nd * N_CLS + sl] = val - lse;
        }
    });
}

// ---------------- link head: trivial scalar combine per edge ----------------
__global__ void k_link(const int* __restrict__ ep, const int* __restrict__ en,
                       const float* __restrict__ bl, float* __restrict__ out) {
    int i = blockIdx.x * blockDim.x + threadIdx.x;
    if (i >= N_EP + N_EN) return;
    float b = bl[0];
    if (i < N_EP) {
        int s = __ldg(&ep[i]), d = __ldg(&ep[N_EP + i]);
        out[i] = __ldg(&g_lta[s]) + __ldg(&g_ltb[d]) + b;
    } else {
        int e2 = i - N_EP;
        int s = __ldg(&en[e2]), d = __ldg(&en[N_EN + e2]);
        out[N_EP + e2] = __ldg(&g_lta[s]) + __ldg(&g_ltb[d]) + b;
    }
}

// ---------------- launch ----------------
extern "C" void kernel_launch(void* const* d_in, const int* in_sizes, int n_in,
                              void* d_out, int out_size) {
    const float* x   = (const float*)d_in[0];
    const int*   ei  = (const int*)d_in[1];
    const int*   ep  = (const int*)d_in[2];
    const int*   en  = (const int*)d_in[3];
    const float* W1  = (const float*)d_in[4];
    const float* b1  = (const float*)d_in[5];
    const float* W2  = (const float*)d_in[6];
    const float* b2  = (const float*)d_in[7];
    const float* Wc  = (const float*)d_in[8];
    const float* bc  = (const float*)d_in[9];
    const float* Wl  = (const float*)d_in[10];
    const float* bl  = (const float*)d_in[11];
    float* out = (float*)d_out;

    const int GEMM_GRID = (N_NODES + 127) / 128;
    const int AGG_GRID  = N_NODES / 16;

    // graph preprocessing (cursor doubles as degree count)
    k_zero<<<(N_NODES + 255) / 256, 256>>>();
    k_bucket<<<(N_EDGES / 4 + 255) / 256, 256>>>(ei);
    k_dinv<<<(N_NODES + 255) / 256, 256>>>();

    // layer 1: tmph = fp16(x @ W1) ; h1 = relu(agg(tmph) + b1) -> fp16
    k_gemm_f16<IN_CH, false><<<GEMM_GRID, 256>>>(x, W1);
    k_agg_relu<<<AGG_GRID, 256>>>(b1);

    // layer 2: tmph = fp16(h1 @ W2) ; agg + node head + link-dot precompute
    k_gemm_f16<HID, true><<<GEMM_GRID, 256>>>(nullptr, W2);
    k_agg_nodehead<<<AGG_GRID, 256>>>(b2, Wc, bc, Wl, out);

    // link head: scalar combine
    k_link<<<(N_EP + N_EN + 255) / 256, 256>>>(ep, en, bl, out + NODE_OUT_ELEMS);
}